// round 17
// baseline (speedup 1.0000x reference)
#include <cuda_runtime.h>
#include <cuda_fp16.h>
#include <cstdint>

#define BTOT  16384
#define T     28
#define INP   28
#define H     64
#define MROWS 64
#define NT    256
#define OUTD  10

// ---- dynamic SMEM layout (byte offsets) ----
// B tile fp16: [kf 0..5][nf 0..31][lane 0..31][8B] = 49152
#define OFF_B    0
#define OFF_BIAS 49152              // 256 f32
#define OFF_XCH  50176              // h exchange: 2 bufs x 4 pairs x 4 slots x 32 lanes x 16B
#define OFF_HF   66560              // h_last f32: 64 x 64 x 4 = 16384
#define SMEM_BYTES (66560 + 16384)
// epilogue scratch reuses dead B region
#define OFF_WFC  0
#define OFF_BFC  2560
#define OFF_PART 4096               // 4*64*10 f32 = 10240 (ends 14336 < 49152)

__device__ __forceinline__ uint32_t smem_u32(const void* p) {
    uint32_t a;
    asm("{ .reg .u64 t; cvta.to.shared.u64 t, %1; cvt.u32.u64 %0, t; }" : "=r"(a) : "l"(p));
    return a;
}
__device__ __forceinline__ void sts32(uint32_t a, uint32_t v) {
    asm volatile("st.shared.b32 [%0], %1;" :: "r"(a), "r"(v) : "memory");
}
__device__ __forceinline__ void sts128(uint32_t a, const uint32_t* r) {
    asm volatile("st.shared.v4.b32 [%0], {%1,%2,%3,%4};"
                 :: "r"(a), "r"(r[0]), "r"(r[1]), "r"(r[2]), "r"(r[3]) : "memory");
}
__device__ __forceinline__ void lds128(uint32_t* r, uint32_t a) {
    asm volatile("ld.shared.v4.b32 {%0,%1,%2,%3}, [%4];"
                 : "=r"(r[0]), "=r"(r[1]), "=r"(r[2]), "=r"(r[3]) : "r"(a));
}
__device__ __forceinline__ void lds64(uint32_t* r, uint32_t a) {
    asm volatile("ld.shared.v2.b32 {%0,%1}, [%2];" : "=r"(r[0]), "=r"(r[1]) : "r"(a));
}
__device__ __forceinline__ float2 lds64f(uint32_t a) {
    float2 v;
    asm volatile("ld.shared.v2.f32 {%0,%1}, [%2];" : "=f"(v.x), "=f"(v.y) : "r"(a));
    return v;
}
// pair barrier: 64 threads (2 warps), ids 1..4
#define BARP(id) asm volatile("bar.sync %0, %1;" :: "r"(id), "r"(64) : "memory")

// pack two f32 into f16x2 (round-to-nearest)
__device__ __forceinline__ uint32_t pack2h(float a, float b) {
    __half2 h2 = __floats2half2_rn(a, b);
    return *reinterpret_cast<uint32_t*>(&h2);
}
// f32 MUFU tanh (value paths)
__device__ __forceinline__ float tanha(float x) {
    float y; asm("tanh.approx.f32 %0, %1;" : "=f"(y) : "f"(x)); return y;
}
// dual-state fp16 sigmoid (multiplier gates only)
__device__ __forceinline__ __half2 tanh2h(__half2 v) {
    uint32_t y, xx = *reinterpret_cast<uint32_t*>(&v);
    asm("tanh.approx.f16x2 %0, %1;" : "=r"(y) : "r"(xx));
    return *reinterpret_cast<__half2*>(&y);
}
__device__ __forceinline__ float2 sigm2(float a, float b) {
    const __half2 h5 = __float2half2_rn(0.5f);
    __half2 s = __hfma2(tanh2h(__floats2half2_rn(0.5f * a, 0.5f * b)), h5, h5);
    return __half22float2(s);
}

// m16n8k16 fp16 MMA, D += A*B (C aliased to D), f32 accumulate
__device__ __forceinline__ void mma16816(float* d, const uint32_t* a, const uint32_t* b) {
    asm volatile(
        "mma.sync.aligned.m16n8k16.row.col.f32.f16.f16.f32 "
        "{%0,%1,%2,%3}, {%4,%5,%6,%7}, {%8,%9}, {%0,%1,%2,%3};"
        : "+f"(d[0]), "+f"(d[1]), "+f"(d[2]), "+f"(d[3])
        : "r"(a[0]), "r"(a[1]), "r"(a[2]), "r"(a[3]), "r"(b[0]), "r"(b[1]));
}

// weight element with K mapping: k 0..27 -> W_ih, 28..31 -> 0, 32..95 -> W_hh
__device__ __forceinline__ float wval(const float* __restrict__ Wih,
                                      const float* __restrict__ Whh, int g, int k) {
    if (k < INP)  return Wih[g * INP + k];
    if (k < 32)   return 0.0f;
    return Whh[g * H + (k - 32)];
}

__global__ void __launch_bounds__(NT, 2) lstm_mma_kernel(
    const float* __restrict__ x,    const float* __restrict__ W_ih,
    const float* __restrict__ W_hh, const float* __restrict__ b_ih,
    const float* __restrict__ b_hh, const float* __restrict__ W_fc,
    const float* __restrict__ b_fc, float* __restrict__ out)
{
    extern __shared__ char sm[];
    const uint32_t sb  = smem_u32(sm);
    const int tid  = threadIdx.x;
    const int wid  = tid >> 5;
    const int pair = wid >> 1;          // 0..3: owns rows pair*16..pair*16+15
    const int mem  = wid & 1;           // member: units mem*32..mem*32+31
    const int lane = tid & 31;
    const int g8   = lane >> 2;
    const int tig  = lane & 3;
    const int b0   = blockIdx.x * MROWS;
    const int row0 = pair * 16;

    // ---- build B fragments (fp16): [kf][nf][lane], all 256 gates ----
    for (int ii = tid; ii < 6 * 32 * 32 * 2; ii += NT) {
        int reg = ii & 1;
        int t_  = (ii >> 1) & 31;
        int nf  = (ii >> 6) & 31;
        int kf  = ii >> 11;
        int k0  = kf * 16 + reg * 8 + 2 * (t_ & 3);
        int g   = 8 * nf + (t_ >> 2);
        float v0 = wval(W_ih, W_hh, g, k0);
        float v1 = wval(W_ih, W_hh, g, k0 + 1);
        uint32_t boff = (uint32_t)(((kf * 32 + nf) * 256) + t_ * 8 + reg * 4);
        sts32(sb + OFF_B + boff, pack2h(v0, v1));
    }
    for (int g = tid; g < 256; g += NT)
        sts32(sb + OFF_BIAS + 4 * g, __float_as_uint(b_ih[g] + b_hh[g]));
    __syncthreads();    // only full-CTA barrier before the loop

    // per-thread recurrent state (16 states: j(4) x rowpair(2) x 2 cols)
    float c[16];
#pragma unroll
    for (int i = 0; i < 16; i++) c[i] = 0.0f;
    // a_h: slots 0,1 = OWN h fragments; 2,3 = partner's (filled by exchange)
    uint32_t a_h[4][4];
#pragma unroll
    for (int i = 0; i < 4; i++)
#pragma unroll
        for (int j = 0; j < 4; j++) a_h[i][j] = 0u;

    const int xb0 = (b0 + row0 + g8) * T * INP;
    const int xb1 = (b0 + row0 + g8 + 8) * T * INP;
    // exchange base for this pair's lane (slot stride 512B, buf stride 8192B)
    const uint32_t xchb = sb + OFF_XCH + (uint32_t)(pair * 4 * 32 + lane) * 16;
    const int barid = pair + 1;

    // =========================== timestep loop ===============================
    for (int t = 0; t < T; t++) {
        const bool last = (t == T - 1);

        // ---- issue x(t) LDGs early ----
        float2 xv[2][2][2];             // [kf][khalf][rowpair]
#pragma unroll
        for (int kf = 0; kf < 2; kf++) {
#pragma unroll
            for (int half = 0; half < 2; half++) {
                int k0 = kf * 16 + half * 8 + 2 * tig;
                if (kf == 1 && half == 1 && tig >= 2) {
                    xv[kf][half][0] = make_float2(0.f, 0.f);
                    xv[kf][half][1] = make_float2(0.f, 0.f);
                } else {
                    xv[kf][half][0] = *reinterpret_cast<const float2*>(x + xb0 + t * INP + k0);
                    xv[kf][half][1] = *reinterpret_cast<const float2*>(x + xb1 + t * INP + k0);
                }
            }
        }

        // ---- D init = bias (16 nf: gates gt, sub j; global nf = gt*8+mem*4+j) ----
        float d[16][4];
#pragma unroll
        for (int gt = 0; gt < 4; gt++) {
#pragma unroll
            for (int j = 0; j < 4; j++) {
                int nfg = gt * 8 + mem * 4 + j;
                float2 b2 = lds64f(sb + OFF_BIAS + (uint32_t)(nfg * 8 + 2 * tig) * 4);
                float* dd = d[gt * 4 + j];
                dd[0] = b2.x; dd[1] = b2.y; dd[2] = b2.x; dd[3] = b2.y;
            }
        }

        // ---- h-part MMA: slot s -> global kf = 2 + ((2*mem + s) & 3) ----
#pragma unroll
        for (int s = 0; s < 4; s++) {
            const int kfg = 2 + ((2 * mem + s) & 3);
#pragma unroll
            for (int gt = 0; gt < 4; gt++) {
#pragma unroll
                for (int j = 0; j < 4; j++) {
                    int nfg = gt * 8 + mem * 4 + j;
                    uint32_t bb[2];
                    lds64(bb, sb + OFF_B + (uint32_t)(((kfg * 32 + nfg) * 256) + lane * 8));
                    mma16816(d[gt * 4 + j], a_h[s], bb);
                }
            }
        }

        // ---- x-part MMA: kf 0..1 ----
        uint32_t a_x[2][4];
#pragma unroll
        for (int kf = 0; kf < 2; kf++)
#pragma unroll
            for (int half = 0; half < 2; half++)
#pragma unroll
                for (int rp = 0; rp < 2; rp++)
                    a_x[kf][rp + 2 * half] = pack2h(xv[kf][half][rp].x, xv[kf][half][rp].y);
#pragma unroll
        for (int kf = 0; kf < 2; kf++) {
#pragma unroll
            for (int gt = 0; gt < 4; gt++) {
#pragma unroll
                for (int j = 0; j < 4; j++) {
                    int nfg = gt * 8 + mem * 4 + j;
                    uint32_t bb[2];
                    lds64(bb, sb + OFF_B + (uint32_t)(((kf * 32 + nfg) * 256) + lane * 8));
                    mma16816(d[gt * 4 + j], a_x[kf], bb);
                }
            }
        }

        // ---- eltwise: own h -> a_h slots 0..1 (kf-half = j&1, slot = j>>1) ----
#pragma unroll
        for (int j = 0; j < 4; j++) {
#pragma unroll
            for (int rp = 0; rp < 2; rp++) {
                const int s0 = 2 * rp;
                const int ci = (j * 2 + rp) * 2;
                float2 gi = sigm2(d[j][s0],      d[j][s0 + 1]);
                float2 gf = sigm2(d[4 + j][s0],  d[4 + j][s0 + 1]);
                float2 go = sigm2(d[12 + j][s0], d[12 + j][s0 + 1]);
                float gg0 = tanha(d[8 + j][s0]);
                float gg1 = tanha(d[8 + j][s0 + 1]);
                float cm0 = fmaf(gf.x, c[ci],     gi.x * gg0);
                float cm1 = fmaf(gf.y, c[ci + 1], gi.y * gg1);
                c[ci] = cm0; c[ci + 1] = cm1;
                float hv0 = go.x * tanha(cm0);
                float hv1 = go.y * tanha(cm1);
                if (!last) {
                    a_h[j >> 1][rp + 2 * (j & 1)] = pack2h(hv0, hv1);
                } else {
                    int r  = row0 + g8 + 8 * rp;
                    int u0 = mem * 32 + j * 8 + 2 * tig;
                    float* hf = reinterpret_cast<float*>(sm + OFF_HF);
                    hf[r * H + u0]     = hv0;
                    hf[r * H + u0 + 1] = hv1;
                }
            }
        }

        // ---- pair exchange: own slots -> smem, partner slots -> a_h[2..3] ----
        if (!last) {
            uint32_t xc = xchb + (uint32_t)((t & 1) * 8192);
            sts128(xc + (uint32_t)(2 * mem) * 512,       a_h[0]);
            sts128(xc + (uint32_t)(2 * mem + 1) * 512,   a_h[1]);
            BARP(barid);
            lds128(a_h[2], xc + (uint32_t)(2 * (1 - mem)) * 512);
            lds128(a_h[3], xc + (uint32_t)(2 * (1 - mem) + 1) * 512);
        }
    }

    // ======================= FC epilogue (fp32 SIMT, 4-way K split) ==========
    __syncthreads();   // all pairs done; h_last complete
    float* smf = reinterpret_cast<float*>(sm);
    const float* hf = reinterpret_cast<const float*>(sm + OFF_HF);
    for (int i = tid; i < OUTD * H; i += NT) smf[OFF_WFC / 4 + i] = W_fc[i];
    if (tid < OUTD) smf[OFF_BFC / 4 + tid] = b_fc[tid];
    __syncthreads();
    {
        const int q = tid >> 6, rr = tid & 63;
        float acc[OUTD];
#pragma unroll
        for (int o = 0; o < OUTD; o++) acc[o] = 0.0f;
#pragma unroll
        for (int p = 0; p < 16; p++) {
            int k = q * 16 + p;
            float hvv = hf[rr * H + k];
#pragma unroll
            for (int o = 0; o < OUTD; o++)
                acc[o] = fmaf(hvv, smf[OFF_WFC / 4 + o * H + k], acc[o]);
        }
#pragma unroll
        for (int o = 0; o < OUTD; o++)
            smf[OFF_PART / 4 + (q * 64 + rr) * OUTD + o] = acc[o];
    }
    __syncthreads();
    for (int i = tid; i < MROWS * OUTD; i += NT) {
        int rr = i / OUTD, o = i - rr * OUTD;
        out[(size_t)(b0 + rr) * OUTD + o] =
            smf[OFF_PART / 4 + rr * OUTD + o]
          + smf[OFF_PART / 4 + (64 + rr) * OUTD + o]
          + smf[OFF_PART / 4 + (128 + rr) * OUTD + o]
          + smf[OFF_PART / 4 + (192 + rr) * OUTD + o]
          + smf[OFF_BFC / 4 + o];
    }
}

extern "C" void kernel_launch(void* const* d_in, const int* in_sizes, int n_in,
                              void* d_out, int out_size) {
    const float* x    = (const float*)d_in[0];
    const float* W_ih = (const float*)d_in[1];
    const float* W_hh = (const float*)d_in[2];
    const float* b_ih = (const float*)d_in[3];
    const float* b_hh = (const float*)d_in[4];
    const float* W_fc = (const float*)d_in[5];
    const float* b_fc = (const float*)d_in[6];

    cudaFuncSetAttribute(lstm_mma_kernel,
                         cudaFuncAttributeMaxDynamicSharedMemorySize, SMEM_BYTES);
    lstm_mma_kernel<<<BTOT / MROWS, NT, SMEM_BYTES>>>(
        x, W_ih, W_hh, b_ih, b_hh, W_fc, b_fc, (float*)d_out);
}